// round 2
// baseline (speedup 1.0000x reference)
#include <cuda_runtime.h>
#include <cstdint>

#define B 64
#define T 256
#define V 128
#define H 1024
#define G 4096              // 4*H
#define M (B*T)             // 16384
#define NCTA 128
#define RTHREADS 512
#define SWS 1036            // padded smem row stride for W (conflict-free, 16B aligned)
#define SMEM_REC ((32*SWS + 64*64) * sizeof(float))

// ---------------- scratch (static device allocations; no cudaMalloc) ----------------
__device__ float g_xg[(size_t)M * G];      // 268 MB: precomputed input gates (reused per layer)
__device__ float g_y0[(size_t)M * H];      // 67 MB: layer0 output sequence
__device__ float g_y1[(size_t)M * H];      // 67 MB: layer1 output sequence
__device__ float g_hbuf[2][B * H];         // double-buffered hidden state
__device__ unsigned g_count;               // grid barrier arrive counter
__device__ unsigned g_epoch;               // grid barrier generation (monotonic across replays)

// ---------------- software grid barrier (all 128 CTAs co-resident) ----------------
__device__ __forceinline__ void gbar(unsigned target) {
    __threadfence();                 // make this thread's writes globally visible
    __syncthreads();
    if (threadIdx.x == 0) {
        unsigned prev = atomicAdd(&g_count, 1u);
        if (prev == NCTA - 1) {
            g_count = 0u;
            __threadfence();
            *((volatile unsigned*)&g_epoch) = target;   // release
        } else {
            while (*((volatile unsigned*)&g_epoch) != target) { __nanosleep(64); }
            __threadfence();                            // acquire
        }
    }
    __syncthreads();
}

// ---------------- generic fp32 GEMM: C[M,N] = A[M,K] * Bw[N,K]^T + bias[N] ----------------
// Requires M%128==0, N%128==0, K%16==0 (true for all three phases here).
__global__ void __launch_bounds__(256) gemm_nt_bias(
    const float* __restrict__ A, const float* __restrict__ Bw,
    const float* __restrict__ bias, float* __restrict__ C,
    int Mm, int Nn, int Kk)
{
    __shared__ float As[16][128];
    __shared__ float Bs[16][128];
    const int tid = threadIdx.x;
    const int tx = tid & 15;
    const int ty = tid >> 4;
    const int ldRow = tid >> 2;          // 0..63
    const int ldCol = (tid & 3) << 2;    // 0,4,8,12
    const float* Ap = A  + (size_t)blockIdx.y * 128 * Kk;
    const float* Bp = Bw + (size_t)blockIdx.x * 128 * Kk;

    float acc[8][8];
#pragma unroll
    for (int i = 0; i < 8; ++i)
#pragma unroll
        for (int jj = 0; jj < 8; ++jj) acc[i][jj] = 0.f;

    for (int kt = 0; kt < Kk; kt += 16) {
#pragma unroll
        for (int p = 0; p < 2; ++p) {
            float4 va = *((const float4*)(Ap + (size_t)(ldRow + p * 64) * Kk + kt + ldCol));
            As[ldCol + 0][ldRow + p * 64] = va.x;
            As[ldCol + 1][ldRow + p * 64] = va.y;
            As[ldCol + 2][ldRow + p * 64] = va.z;
            As[ldCol + 3][ldRow + p * 64] = va.w;
            float4 vb = *((const float4*)(Bp + (size_t)(ldRow + p * 64) * Kk + kt + ldCol));
            Bs[ldCol + 0][ldRow + p * 64] = vb.x;
            Bs[ldCol + 1][ldRow + p * 64] = vb.y;
            Bs[ldCol + 2][ldRow + p * 64] = vb.z;
            Bs[ldCol + 3][ldRow + p * 64] = vb.w;
        }
        __syncthreads();
#pragma unroll
        for (int k = 0; k < 16; ++k) {
            float4 a0 = *((const float4*)&As[k][ty * 8]);
            float4 a1 = *((const float4*)&As[k][ty * 8 + 4]);
            float4 b0 = *((const float4*)&Bs[k][tx * 8]);
            float4 b1 = *((const float4*)&Bs[k][tx * 8 + 4]);
            float ra[8] = {a0.x, a0.y, a0.z, a0.w, a1.x, a1.y, a1.z, a1.w};
            float rb[8] = {b0.x, b0.y, b0.z, b0.w, b1.x, b1.y, b1.z, b1.w};
#pragma unroll
            for (int i = 0; i < 8; ++i)
#pragma unroll
                for (int jj = 0; jj < 8; ++jj)
                    acc[i][jj] = fmaf(ra[i], rb[jj], acc[i][jj]);
        }
        __syncthreads();
    }

    const int row0 = blockIdx.y * 128 + ty * 8;
    const int col0 = blockIdx.x * 128 + tx * 8;
#pragma unroll
    for (int i = 0; i < 8; ++i) {
#pragma unroll
        for (int jj = 0; jj < 8; jj += 4) {
            float4 o;
            o.x = acc[i][jj + 0] + bias[col0 + jj + 0];
            o.y = acc[i][jj + 1] + bias[col0 + jj + 1];
            o.z = acc[i][jj + 2] + bias[col0 + jj + 2];
            o.w = acc[i][jj + 3] + bias[col0 + jj + 3];
            *((float4*)(C + (size_t)(row0 + i) * Nn + col0 + jj)) = o;
        }
    }
}

// ---------------- persistent LSTM recurrence (one launch per layer) ----------------
// 128 CTAs x 512 threads; CTA owns hidden units [cta*8, cta*8+8) -> 32 gate rows
// of W_hh cached in smem. One grid barrier per timestep; h double-buffered in global.
__global__ void __launch_bounds__(RTHREADS, 1) lstm_rec(
    const float* __restrict__ xg,    // [B,T,4H] precomputed x@W_ih^T + b
    const float* __restrict__ Whh,   // [4H,H]
    const float* __restrict__ h0,    // [B,H] this layer's initial h
    const float* __restrict__ c0,    // [B,H]
    float* __restrict__ y,           // [B,T,H] output sequence
    float* __restrict__ hT,          // [B,H] final h
    float* __restrict__ cT)          // [B,H] final c
{
    extern __shared__ float smem[];
    float* sW = smem;                 // [32][SWS]
    float* sH = smem + 32 * SWS;      // [64][64] h tile
    const int tid  = threadIdx.x;
    const int cta  = blockIdx.x;
    const int lane = tid & 31;
    const int w    = tid >> 5;        // warp 0..15
    const int q    = lane >> 3;       // gate quadrant 0..3 (i,f,g,o)
    const int j    = lane & 7;        // hidden unit within chunk
    const int jg   = cta * 8 + j;     // global hidden index

    const unsigned e0 = *((volatile unsigned*)&g_epoch);

    // load this CTA's 32 gate rows of W_hh into smem (padded stride: conflict-free)
    for (int idx = tid; idx < 32 * 256; idx += RTHREADS) {
        int r  = idx >> 8;                 // 0..31 : r = qr*8 + jr
        int c4 = (idx & 255) * 4;
        int Rg = (r >> 3) * H + cta * 8 + (r & 7);
        float4 v = *((const float4*)(Whh + (size_t)Rg * H + c4));
        sW[r * SWS + c4 + 0] = v.x;
        sW[r * SWS + c4 + 1] = v.y;
        sW[r * SWS + c4 + 2] = v.z;
        sW[r * SWS + c4 + 3] = v.w;
    }

    // init h double-buffer slot 0 (this CTA's columns for all batches) + c in regs
    float creg[4];
#pragma unroll
    for (int m = 0; m < 4; ++m) {
        int b = w + 16 * m;
        if (lane < 8) {
            g_hbuf[0][b * H + jg] = h0[b * H + jg];
            creg[m] = c0[b * H + jg];
        }
    }
    gbar(e0 + 1);

    for (int t = 0; t < T; ++t) {
        const float* hb = g_hbuf[t & 1];
        float* hn = g_hbuf[(t + 1) & 1];
        float acc[4] = {0.f, 0.f, 0.f, 0.f};
        const float* wrow = sW + lane * SWS;

        for (int kt = 0; kt < 16; ++kt) {
            __syncthreads();
            // stage h[0:64][kt*64 : kt*64+64] into smem (coalesced)
#pragma unroll
            for (int p = 0; p < 2; ++p) {
                int idx = tid * 2 + p;
                int row = idx >> 4;
                int c4  = (idx & 15) * 4;
                float4 v = *((const float4*)(hb + row * H + kt * 64 + c4));
                sH[row * 64 + c4 + 0] = v.x;
                sH[row * 64 + c4 + 1] = v.y;
                sH[row * 64 + c4 + 2] = v.z;
                sH[row * 64 + c4 + 3] = v.w;
            }
            __syncthreads();
            // lane = gate row r; warp broadcasts h rows (b = w + 16m)
#pragma unroll
            for (int kk = 0; kk < 64; kk += 4) {
                const float4 wv = *((const float4*)(wrow + kt * 64 + kk));
#pragma unroll
                for (int m = 0; m < 4; ++m) {
                    const float4 av = *((const float4*)(sH + (w + 16 * m) * 64 + kk));
                    acc[m] = fmaf(wv.x, av.x, acc[m]);
                    acc[m] = fmaf(wv.y, av.y, acc[m]);
                    acc[m] = fmaf(wv.z, av.z, acc[m]);
                    acc[m] = fmaf(wv.w, av.w, acc[m]);
                }
            }
        }

        // gates -> activations -> c,h update (lanes 0..7 own outputs, shuffles gather i,f,g,o)
#pragma unroll
        for (int m = 0; m < 4; ++m) {
            int b = w + 16 * m;
            float val = acc[m] + xg[((size_t)b * T + t) * G + q * H + jg];
            float iv = __shfl_sync(0xffffffffu, val, j);
            float fv = __shfl_sync(0xffffffffu, val, j + 8);
            float gv = __shfl_sync(0xffffffffu, val, j + 16);
            float ov = __shfl_sync(0xffffffffu, val, j + 24);
            if (lane < 8) {
                float ig = 1.f / (1.f + expf(-iv));
                float fg = 1.f / (1.f + expf(-fv));
                float gg = tanhf(gv);
                float og = 1.f / (1.f + expf(-ov));
                float cv = fg * creg[m] + ig * gg;
                creg[m] = cv;
                float hv = og * tanhf(cv);
                hn[b * H + jg] = hv;
                y[((size_t)b * T + t) * H + jg] = hv;
                if (t == T - 1) { hT[b * H + jg] = hv; cT[b * H + jg] = cv; }
            }
        }
        gbar(e0 + 2 + t);
    }
}

// ---------------- launch ----------------
extern "C" void kernel_launch(void* const* d_in, const int* in_sizes, int n_in,
                              void* d_out, int out_size) {
    const float* x    = (const float*)d_in[0];
    const float* h0   = (const float*)d_in[1];
    const float* c0   = (const float*)d_in[2];
    const float* Wih0 = (const float*)d_in[3];
    const float* Whh0 = (const float*)d_in[4];
    const float* b0   = (const float*)d_in[5];
    const float* Wih1 = (const float*)d_in[6];
    const float* Whh1 = (const float*)d_in[7];
    const float* b1   = (const float*)d_in[8];
    const float* Wout = (const float*)d_in[9];
    const float* bout = (const float*)d_in[10];

    float* out     = (float*)d_out;
    float* out_act = out;                          // [M, V]
    float* out_h   = out + (size_t)M * V;          // [2, B, H]
    float* out_c   = out_h + 2 * B * H;            // [2, B, H]

    float *xg, *y0, *y1;
    cudaGetSymbolAddress((void**)&xg, g_xg);
    cudaGetSymbolAddress((void**)&y0, g_y0);
    cudaGetSymbolAddress((void**)&y1, g_y1);

    cudaFuncSetAttribute(lstm_rec, cudaFuncAttributeMaxDynamicSharedMemorySize, (int)SMEM_REC);

    // Phase A: xg0 = x @ W_ih0^T + b0     [16384,128] x [4096,128]^T
    gemm_nt_bias<<<dim3(G / 128, M / 128), 256>>>(x, Wih0, b0, xg, M, G, V);
    // Layer 0 recurrence
    lstm_rec<<<NCTA, RTHREADS, SMEM_REC>>>(xg, Whh0, h0, c0, y0, out_h, out_c);
    // Phase C: xg1 = y0 @ W_ih1^T + b1    [16384,1024] x [4096,1024]^T
    gemm_nt_bias<<<dim3(G / 128, M / 128), 256>>>(y0, Wih1, b1, xg, M, G, H);
    // Layer 1 recurrence
    lstm_rec<<<NCTA, RTHREADS, SMEM_REC>>>(xg, Whh1, h0 + B * H, c0 + B * H, y1,
                                           out_h + B * H, out_c + B * H);
    // Head: act = y1 @ W_out^T + b_out    [16384,1024] x [128,1024]^T
    gemm_nt_bias<<<dim3(V / 128, M / 128), 256>>>(y1, Wout, bout, out_act, M, V, H);
}

// round 4
// speedup vs baseline: 1.1140x; 1.1140x over previous
#include <cuda_runtime.h>
#include <cuda_bf16.h>
#include <cstdint>

#define B 64
#define T 256
#define V 128
#define H 1024
#define G 4096              // 4*H
#define M (B*T)             // 16384
#define NCTA 128
#define RTHREADS 512
#define SWS 1036            // padded smem row stride for W (conflict-free, 16B aligned)
#define SMEM_REC ((32*SWS + 64*64) * sizeof(float))

// ---------------- mma GEMM tile config ----------------
#define GM_BM 128
#define GM_BN 128
#define GM_BK 64                         // bf16 elems per K-chunk (128B per row)
#define GM_TILE_BYTES (128 * 128)        // one operand tile: 128 rows x 128B = 16KB
#define GM_BUF_BYTES (4 * GM_TILE_BYTES) // Ahi, Alo, Bhi, Blo = 64KB
#define SMEM_GM (2 * GM_BUF_BYTES)       // double buffered = 128KB

// ---------------- scratch (static device arrays; no cudaMalloc) ----------------
__device__ float g_xg[(size_t)M * G];            // precomputed input gates
__device__ float g_y0[(size_t)M * H];            // layer0 output sequence
__device__ float g_y1[(size_t)M * H];            // layer1 output sequence
__device__ __nv_bfloat16 g_act_hi[(size_t)M * H];// split activations
__device__ __nv_bfloat16 g_act_lo[(size_t)M * H];
__device__ __nv_bfloat16 g_w_hi[(size_t)G * H];  // split weights
__device__ __nv_bfloat16 g_w_lo[(size_t)G * H];
__device__ float g_hbuf[2][B * H];               // double-buffered hidden state
__device__ unsigned g_count;                     // grid barrier arrive counter
__device__ unsigned g_epoch;                     // grid barrier generation

// ---------------- PTX helpers (sm_100 base target: mma.sync/ldmatrix/cp.async) ----------------
__device__ __forceinline__ uint32_t smem_u32(const void* p) {
    uint32_t a;
    asm("{ .reg .u64 t; cvta.to.shared.u64 t, %1; cvt.u32.u64 %0, t; }" : "=r"(a) : "l"(p));
    return a;
}
__device__ __forceinline__ void cp_async16(uint32_t saddr, const void* gaddr) {
    asm volatile("cp.async.cg.shared.global [%0], [%1], 16;" :: "r"(saddr), "l"(gaddr) : "memory");
}
__device__ __forceinline__ void cp_commit() {
    asm volatile("cp.async.commit_group;" ::: "memory");
}
template <int N>
__device__ __forceinline__ void cp_wait() {
    asm volatile("cp.async.wait_group %0;" :: "n"(N) : "memory");
}
__device__ __forceinline__ void ldsm4(uint32_t* r, uint32_t addr) {
    asm volatile("ldmatrix.sync.aligned.m8n8.x4.shared.b16 {%0,%1,%2,%3}, [%4];"
        : "=r"(r[0]), "=r"(r[1]), "=r"(r[2]), "=r"(r[3]) : "r"(addr));
}
__device__ __forceinline__ void mma16816(float* d, const uint32_t* a, const uint32_t* b) {
    asm volatile("mma.sync.aligned.m16n8k16.row.col.f32.bf16.bf16.f32 "
        "{%0,%1,%2,%3}, {%4,%5,%6,%7}, {%8,%9}, {%0,%1,%2,%3};"
        : "+f"(d[0]), "+f"(d[1]), "+f"(d[2]), "+f"(d[3])
        : "r"(a[0]), "r"(a[1]), "r"(a[2]), "r"(a[3]), "r"(b[0]), "r"(b[1]));
}

// ---------------- software grid barrier (all 128 CTAs co-resident) ----------------
__device__ __forceinline__ void gbar(unsigned target) {
    __threadfence();
    __syncthreads();
    if (threadIdx.x == 0) {
        unsigned prev = atomicAdd(&g_count, 1u);
        if (prev == NCTA - 1) {
            g_count = 0u;
            __threadfence();
            *((volatile unsigned*)&g_epoch) = target;
        } else {
            while (*((volatile unsigned*)&g_epoch) != target) { __nanosleep(64); }
            __threadfence();
        }
    }
    __syncthreads();
}

// ---------------- fp32 -> bf16 hi/lo split (elementwise) ----------------
__global__ void __launch_bounds__(256) split_bf16(
    const float* __restrict__ in, __nv_bfloat16* __restrict__ hi,
    __nv_bfloat16* __restrict__ lo, int n4)
{
    int i = blockIdx.x * 256 + threadIdx.x;
    if (i >= n4) return;
    float4 v = ((const float4*)in)[i];
    __nv_bfloat16 h0 = __float2bfloat16(v.x);
    __nv_bfloat16 h1 = __float2bfloat16(v.y);
    __nv_bfloat16 h2 = __float2bfloat16(v.z);
    __nv_bfloat16 h3 = __float2bfloat16(v.w);
    __nv_bfloat16 l0 = __float2bfloat16(v.x - __bfloat162float(h0));
    __nv_bfloat16 l1 = __float2bfloat16(v.y - __bfloat162float(h1));
    __nv_bfloat16 l2 = __float2bfloat16(v.z - __bfloat162float(h2));
    __nv_bfloat16 l3 = __float2bfloat16(v.w - __bfloat162float(h3));
    ((__nv_bfloat162*)hi)[2 * i]     = __nv_bfloat162(h0, h1);
    ((__nv_bfloat162*)hi)[2 * i + 1] = __nv_bfloat162(h2, h3);
    ((__nv_bfloat162*)lo)[2 * i]     = __nv_bfloat162(l0, l1);
    ((__nv_bfloat162*)lo)[2 * i + 1] = __nv_bfloat162(l2, l3);
}

// ---------------- split-bf16 tensor GEMM: C[M,N] = A[M,K] * Bw[N,K]^T + bias ----------------
// 256 threads, CTA tile 128x128, warp tile 64x32, K-chunk 64, cp.async double buffer.
// Requires M%128==0, N%128==0, K%128==0.
__global__ void __launch_bounds__(256, 1) gemm_mma(
    const __nv_bfloat16* __restrict__ Ahi, const __nv_bfloat16* __restrict__ Alo,
    const __nv_bfloat16* __restrict__ Bhi, const __nv_bfloat16* __restrict__ Blo,
    const float* __restrict__ bias, float* __restrict__ C, int Nn, int Kk)
{
    extern __shared__ char smem[];
    const uint32_t sb = smem_u32(smem);
    const int tid  = threadIdx.x;
    const int wid  = tid >> 5;
    const int lane = tid & 31;
    const int m0 = blockIdx.y * GM_BM;
    const int n0 = blockIdx.x * GM_BN;
    const int wm = (wid >> 2) * 64;     // warp m-offset in CTA tile
    const int wn = (wid & 3) * 32;      // warp n-offset

    const char* srcs[4];
    srcs[0] = (const char*)(Ahi + (size_t)m0 * Kk);
    srcs[1] = (const char*)(Alo + (size_t)m0 * Kk);
    srcs[2] = (const char*)(Bhi + (size_t)n0 * Kk);
    srcs[3] = (const char*)(Blo + (size_t)n0 * Kk);
    const size_t rstride = (size_t)Kk * 2;   // bytes per row
    const int nk = Kk / GM_BK;

    // chunk loader: 4 tiles x 128 rows x 128B, 16B per cp.async, XOR swizzle
    auto load_chunk = [&](int kt, int buf) {
        const uint32_t base = sb + buf * GM_BUF_BYTES;
#pragma unroll
        for (int tgt = 0; tgt < 4; ++tgt) {
            const char* gp = srcs[tgt] + (size_t)kt * 128;
            const uint32_t tb = base + tgt * GM_TILE_BYTES;
#pragma unroll
            for (int p = 0; p < 4; ++p) {
                int idx = tid + p * 256;        // 0..1023
                int row = idx >> 3;
                int c16 = (idx & 7) << 4;       // byte col 0..112
                cp_async16(tb + row * 128 + (c16 ^ ((row & 7) << 4)),
                           gp + (size_t)row * rstride + c16);
            }
        }
        cp_commit();
    };

    float acc[4][4][4];
#pragma unroll
    for (int i = 0; i < 4; ++i)
#pragma unroll
        for (int j = 0; j < 4; ++j)
#pragma unroll
            for (int k = 0; k < 4; ++k) acc[i][j][k] = 0.f;

    load_chunk(0, 0);

    // precomputed ldmatrix lane addressing (within a tile)
    const int a_row = lane & 15;                       // + m-tile offset
    const int a_csel = ((lane >> 4) & 1) << 4;         // byte offset 0/16 within k-step
    const int b_row = (lane & 7) + (((lane >> 4) & 1) << 3);
    const int b_csel = ((lane >> 3) & 1) << 4;

    for (int kt = 0; kt < nk; ++kt) {
        const int buf = kt & 1;
        if (kt + 1 < nk) { load_chunk(kt + 1, buf ^ 1); cp_wait<1>(); }
        else             { cp_wait<0>(); }
        __syncthreads();

        const uint32_t base = sb + buf * GM_BUF_BYTES;
        const uint32_t aHiB = base;
        const uint32_t aLoB = base + GM_TILE_BYTES;
        const uint32_t bHiB = base + 2 * GM_TILE_BYTES;
        const uint32_t bLoB = base + 3 * GM_TILE_BYTES;

#pragma unroll
        for (int ks = 0; ks < 4; ++ks) {               // four k16 steps per chunk
            const int acol = ks * 32 + a_csel;
            const int bcol = ks * 32 + b_csel;
            uint32_t ahi[4][4], alo[4][4];
#pragma unroll
            for (int mt = 0; mt < 4; ++mt) {
                int row = wm + mt * 16 + a_row;
                uint32_t off = row * 128 + (acol ^ ((row & 7) << 4));
                ldsm4(ahi[mt], aHiB + off);
                ldsm4(alo[mt], aLoB + off);
            }
            uint32_t bhi[2][4], blo[2][4];
#pragma unroll
            for (int np = 0; np < 2; ++np) {           // each x4 covers 16 n (2 n-tiles)
                int row = wn + np * 16 + b_row;
                uint32_t off = row * 128 + (bcol ^ ((row & 7) << 4));
                ldsm4(bhi[np], bHiB + off);
                ldsm4(blo[np], bLoB + off);
            }
#pragma unroll
            for (int mt = 0; mt < 4; ++mt)
#pragma unroll
                for (int np = 0; np < 2; ++np)
#pragma unroll
                    for (int s = 0; s < 2; ++s) {
                        int nt = np * 2 + s;
                        mma16816(acc[mt][nt], ahi[mt], &bhi[np][s * 2]);
                        mma16816(acc[mt][nt], ahi[mt], &blo[np][s * 2]);
                        mma16816(acc[mt][nt], alo[mt], &bhi[np][s * 2]);
                    }
        }
        __syncthreads();
    }

    // epilogue: bias add + store (fragment layout: d0,d1 @ (r, c..c+1); d2,d3 @ (r+8, c..c+1))
#pragma unroll
    for (int mt = 0; mt < 4; ++mt) {
        const int rg = m0 + wm + mt * 16 + (lane >> 2);
#pragma unroll
        for (int nt = 0; nt < 4; ++nt) {
            const int cg = n0 + wn + nt * 8 + (lane & 3) * 2;
            const float2 bv = *(const float2*)(bias + cg);
            float2 o0, o1;
            o0.x = acc[mt][nt][0] + bv.x;
            o0.y = acc[mt][nt][1] + bv.y;
            o1.x = acc[mt][nt][2] + bv.x;
            o1.y = acc[mt][nt][3] + bv.y;
            *(float2*)(C + (size_t)rg * Nn + cg) = o0;
            *(float2*)(C + (size_t)(rg + 8) * Nn + cg) = o1;
        }
    }
}

// ---------------- persistent LSTM recurrence (unchanged from R2) ----------------
__global__ void __launch_bounds__(RTHREADS, 1) lstm_rec(
    const float* __restrict__ xg, const float* __restrict__ Whh,
    const float* __restrict__ h0, const float* __restrict__ c0,
    float* __restrict__ y, float* __restrict__ hT, float* __restrict__ cT)
{
    extern __shared__ float smemf[];
    float* sW = smemf;
    float* sH = smemf + 32 * SWS;
    const int tid  = threadIdx.x;
    const int cta  = blockIdx.x;
    const int lane = tid & 31;
    const int w    = tid >> 5;
    const int q    = lane >> 3;
    const int j    = lane & 7;
    const int jg   = cta * 8 + j;

    const unsigned e0 = *((volatile unsigned*)&g_epoch);

    for (int idx = tid; idx < 32 * 256; idx += RTHREADS) {
        int r  = idx >> 8;
        int c4 = (idx & 255) * 4;
        int Rg = (r >> 3) * H + cta * 8 + (r & 7);
        float4 v = *((const float4*)(Whh + (size_t)Rg * H + c4));
        sW[r * SWS + c4 + 0] = v.x;
        sW[r * SWS + c4 + 1] = v.y;
        sW[r * SWS + c4 + 2] = v.z;
        sW[r * SWS + c4 + 3] = v.w;
    }

    float creg[4];
#pragma unroll
    for (int m = 0; m < 4; ++m) {
        int b = w + 16 * m;
        if (lane < 8) {
            g_hbuf[0][b * H + jg] = h0[b * H + jg];
            creg[m] = c0[b * H + jg];
        }
    }
    gbar(e0 + 1);

    for (int t = 0; t < T; ++t) {
        const float* hb = g_hbuf[t & 1];
        float* hn = g_hbuf[(t + 1) & 1];
        float acc[4] = {0.f, 0.f, 0.f, 0.f};
        const float* wrow = sW + lane * SWS;

        for (int kt = 0; kt < 16; ++kt) {
            __syncthreads();
#pragma unroll
            for (int p = 0; p < 2; ++p) {
                int idx = tid * 2 + p;
                int row = idx >> 4;
                int c4  = (idx & 15) * 4;
                float4 v = *((const float4*)(hb + row * H + kt * 64 + c4));
                sH[row * 64 + c4 + 0] = v.x;
                sH[row * 64 + c4 + 1] = v.y;
                sH[row * 64 + c4 + 2] = v.z;
                sH[row * 64 + c4 + 3] = v.w;
            }
            __syncthreads();
#pragma unroll
            for (int kk = 0; kk < 64; kk += 4) {
                const float4 wv = *((const float4*)(wrow + kt * 64 + kk));
#pragma unroll
                for (int m = 0; m < 4; ++m) {
                    const float4 av = *((const float4*)(sH + (w + 16 * m) * 64 + kk));
                    acc[m] = fmaf(wv.x, av.x, acc[m]);
                    acc[m] = fmaf(wv.y, av.y, acc[m]);
                    acc[m] = fmaf(wv.z, av.z, acc[m]);
                    acc[m] = fmaf(wv.w, av.w, acc[m]);
                }
            }
        }

#pragma unroll
        for (int m = 0; m < 4; ++m) {
            int b = w + 16 * m;
            float val = acc[m] + xg[((size_t)b * T + t) * G + q * H + jg];
            float iv = __shfl_sync(0xffffffffu, val, j);
            float fv = __shfl_sync(0xffffffffu, val, j + 8);
            float gv = __shfl_sync(0xffffffffu, val, j + 16);
            float ov = __shfl_sync(0xffffffffu, val, j + 24);
            if (lane < 8) {
                float ig = 1.f / (1.f + expf(-iv));
                float fg = 1.f / (1.f + expf(-fv));
                float gg = tanhf(gv);
                float og = 1.f / (1.f + expf(-ov));
                float cv = fg * creg[m] + ig * gg;
                creg[m] = cv;
                float hv = og * tanhf(cv);
                hn[b * H + jg] = hv;
                y[((size_t)b * T + t) * H + jg] = hv;
                if (t == T - 1) { hT[b * H + jg] = hv; cT[b * H + jg] = cv; }
            }
        }
        gbar(e0 + 2 + t);
    }
}

// ---------------- launch ----------------
extern "C" void kernel_launch(void* const* d_in, const int* in_sizes, int n_in,
                              void* d_out, int out_size) {
    const float* x    = (const float*)d_in[0];
    const float* h0   = (const float*)d_in[1];
    const float* c0   = (const float*)d_in[2];
    const float* Wih0 = (const float*)d_in[3];
    const float* Whh0 = (const float*)d_in[4];
    const float* b0   = (const float*)d_in[5];
    const float* Wih1 = (const float*)d_in[6];
    const float* Whh1 = (const float*)d_in[7];
    const float* b1   = (const float*)d_in[8];
    const float* Wout = (const float*)d_in[9];
    const float* bout = (const float*)d_in[10];

    float* out     = (float*)d_out;
    float* out_act = out;
    float* out_h   = out + (size_t)M * V;
    float* out_c   = out_h + 2 * B * H;

    float *xg, *y0, *y1;
    __nv_bfloat16 *ahi, *alo, *whi, *wlo;
    cudaGetSymbolAddress((void**)&xg, g_xg);
    cudaGetSymbolAddress((void**)&y0, g_y0);
    cudaGetSymbolAddress((void**)&y1, g_y1);
    cudaGetSymbolAddress((void**)&ahi, g_act_hi);
    cudaGetSymbolAddress((void**)&alo, g_act_lo);
    cudaGetSymbolAddress((void**)&whi, g_w_hi);
    cudaGetSymbolAddress((void**)&wlo, g_w_lo);

    cudaFuncSetAttribute(lstm_rec, cudaFuncAttributeMaxDynamicSharedMemorySize, (int)SMEM_REC);
    cudaFuncSetAttribute(gemm_mma, cudaFuncAttributeMaxDynamicSharedMemorySize, (int)SMEM_GM);

    // ---- Layer 0 input GEMM: xg = x @ Wih0^T + b0  (K=128) ----
    split_bf16<<<(M * V / 4 + 255) / 256, 256>>>(x, ahi, alo, M * V / 4);
    split_bf16<<<(G * V / 4 + 255) / 256, 256>>>(Wih0, whi, wlo, G * V / 4);
    gemm_mma<<<dim3(G / 128, M / 128), 256, SMEM_GM>>>(ahi, alo, whi, wlo, b0, xg, G, V);
    // ---- Layer 0 recurrence ----
    lstm_rec<<<NCTA, RTHREADS, SMEM_REC>>>(xg, Whh0, h0, c0, y0, out_h, out_c);
    // ---- Layer 1 input GEMM: xg = y0 @ Wih1^T + b1  (K=1024) ----
    split_bf16<<<(M * H / 4 + 255) / 256, 256>>>(y0, ahi, alo, M * H / 4);
    split_bf16<<<(G * H / 4 + 255) / 256, 256>>>(Wih1, whi, wlo, G * H / 4);
    gemm_mma<<<dim3(G / 128, M / 128), 256, SMEM_GM>>>(ahi, alo, whi, wlo, b1, xg, G, H);
    // ---- Layer 1 recurrence ----
    lstm_rec<<<NCTA, RTHREADS, SMEM_REC>>>(xg, Whh1, h0 + B * H, c0 + B * H, y1,
                                           out_h + B * H, out_c + B * H);
    // ---- Head: act = y1 @ Wout^T + b_out  (N=128, K=1024) ----
    split_bf16<<<(M * H / 4 + 255) / 256, 256>>>(y1, ahi, alo, M * H / 4);
    split_bf16<<<(V * H / 4 + 255) / 256, 256>>>(Wout, whi, wlo, V * H / 4);
    gemm_mma<<<dim3(V / 128, M / 128), 256, SMEM_GM>>>(ahi, alo, whi, wlo, bout, out_act, V, H);
}

// round 5
// speedup vs baseline: 3.7470x; 3.3635x over previous
#include <cuda_runtime.h>
#include <cuda_bf16.h>
#include <cstdint>

#define B 64
#define T 256
#define V 128
#define H 1024
#define G 4096              // 4*H
#define M (B*T)             // 16384
#define NCTA 128

// ---------------- feed-forward mma GEMM tile config (unchanged, validated R4) ----------------
#define GM_BM 128
#define GM_BN 128
#define GM_BK 64
#define GM_TILE_BYTES (128 * 128)
#define GM_BUF_BYTES (4 * GM_TILE_BYTES)
#define SMEM_GM (2 * GM_BUF_BYTES)

// ---------------- recurrence smem layout (bytes) ----------------
// W: [2 comp][8 kc][32 rows][256B]  comp stride 64KB          -> 128 KB
// H: [2 buf][2 comp][64 rows][256B] buf stride 32KB, comp 16KB -> 64 KB
// RES: 64 x 40 fp32                                            -> 10 KB
#define SM_W   0
#define SM_Hb  131072
#define SM_RES 196608
#define SMEM_TC (SM_RES + 64 * 40 * 4)

// ---------------- scratch (static device arrays; no cudaMalloc) ----------------
__device__ float g_xg[(size_t)M * G];
__device__ float g_y0[(size_t)M * H];
__device__ float g_y1[(size_t)M * H];
__device__ __align__(16) __nv_bfloat16 g_act_hi[(size_t)M * H];
__device__ __align__(16) __nv_bfloat16 g_act_lo[(size_t)M * H];
__device__ __align__(16) __nv_bfloat16 g_w_hi[(size_t)G * H];
__device__ __align__(16) __nv_bfloat16 g_w_lo[(size_t)G * H];
__device__ __align__(16) __nv_bfloat16 g_hb16[2][2][B * H];   // [buf][hi/lo][64*1024]
__device__ unsigned g_count;
__device__ unsigned g_epoch;

// ---------------- PTX helpers (base sm_100: mma.sync/ldmatrix/cp.async) ----------------
__device__ __forceinline__ uint32_t smem_u32(const void* p) {
    uint32_t a;
    asm("{ .reg .u64 t; cvta.to.shared.u64 t, %1; cvt.u32.u64 %0, t; }" : "=r"(a) : "l"(p));
    return a;
}
__device__ __forceinline__ void cp_async16(uint32_t saddr, const void* gaddr) {
    asm volatile("cp.async.cg.shared.global [%0], [%1], 16;" :: "r"(saddr), "l"(gaddr) : "memory");
}
__device__ __forceinline__ void cp_commit() {
    asm volatile("cp.async.commit_group;" ::: "memory");
}
template <int N>
__device__ __forceinline__ void cp_wait() {
    asm volatile("cp.async.wait_group %0;" :: "n"(N) : "memory");
}
__device__ __forceinline__ void ldsm4(uint32_t* r, uint32_t addr) {
    asm volatile("ldmatrix.sync.aligned.m8n8.x4.shared.b16 {%0,%1,%2,%3}, [%4];"
        : "=r"(r[0]), "=r"(r[1]), "=r"(r[2]), "=r"(r[3]) : "r"(addr));
}
__device__ __forceinline__ void mma16816(float* d, const uint32_t* a, const uint32_t* b) {
    asm volatile("mma.sync.aligned.m16n8k16.row.col.f32.bf16.bf16.f32 "
        "{%0,%1,%2,%3}, {%4,%5,%6,%7}, {%8,%9}, {%0,%1,%2,%3};"
        : "+f"(d[0]), "+f"(d[1]), "+f"(d[2]), "+f"(d[3])
        : "r"(a[0]), "r"(a[1]), "r"(a[2]), "r"(a[3]), "r"(b[0]), "r"(b[1]));
}

// ---------------- software grid barrier (all 128 CTAs co-resident) ----------------
__device__ __forceinline__ void gbar(unsigned target) {
    __threadfence();
    __syncthreads();
    if (threadIdx.x == 0) {
        unsigned prev = atomicAdd(&g_count, 1u);
        if (prev == NCTA - 1) {
            g_count = 0u;
            __threadfence();
            *((volatile unsigned*)&g_epoch) = target;
        } else {
            while (*((volatile unsigned*)&g_epoch) != target) { __nanosleep(64); }
            __threadfence();
        }
    }
    __syncthreads();
}

// ---------------- fp32 -> bf16 hi/lo split (elementwise) ----------------
__global__ void __launch_bounds__(256) split_bf16(
    const float* __restrict__ in, __nv_bfloat16* __restrict__ hi,
    __nv_bfloat16* __restrict__ lo, int n4)
{
    int i = blockIdx.x * 256 + threadIdx.x;
    if (i >= n4) return;
    float4 v = ((const float4*)in)[i];
    __nv_bfloat16 h0 = __float2bfloat16(v.x);
    __nv_bfloat16 h1 = __float2bfloat16(v.y);
    __nv_bfloat16 h2 = __float2bfloat16(v.z);
    __nv_bfloat16 h3 = __float2bfloat16(v.w);
    __nv_bfloat16 l0 = __float2bfloat16(v.x - __bfloat162float(h0));
    __nv_bfloat16 l1 = __float2bfloat16(v.y - __bfloat162float(h1));
    __nv_bfloat16 l2 = __float2bfloat16(v.z - __bfloat162float(h2));
    __nv_bfloat16 l3 = __float2bfloat16(v.w - __bfloat162float(h3));
    ((__nv_bfloat162*)hi)[2 * i]     = __nv_bfloat162(h0, h1);
    ((__nv_bfloat162*)hi)[2 * i + 1] = __nv_bfloat162(h2, h3);
    ((__nv_bfloat162*)lo)[2 * i]     = __nv_bfloat162(l0, l1);
    ((__nv_bfloat162*)lo)[2 * i + 1] = __nv_bfloat162(l2, l3);
}

// ---------------- split-bf16 tensor GEMM (unchanged from R4, validated) ----------------
__global__ void __launch_bounds__(256, 1) gemm_mma(
    const __nv_bfloat16* __restrict__ Ahi, const __nv_bfloat16* __restrict__ Alo,
    const __nv_bfloat16* __restrict__ Bhi, const __nv_bfloat16* __restrict__ Blo,
    const float* __restrict__ bias, float* __restrict__ C, int Nn, int Kk)
{
    extern __shared__ char smem[];
    const uint32_t sb = smem_u32(smem);
    const int tid  = threadIdx.x;
    const int wid  = tid >> 5;
    const int lane = tid & 31;
    const int m0 = blockIdx.y * GM_BM;
    const int n0 = blockIdx.x * GM_BN;
    const int wm = (wid >> 2) * 64;
    const int wn = (wid & 3) * 32;

    const char* srcs[4];
    srcs[0] = (const char*)(Ahi + (size_t)m0 * Kk);
    srcs[1] = (const char*)(Alo + (size_t)m0 * Kk);
    srcs[2] = (const char*)(Bhi + (size_t)n0 * Kk);
    srcs[3] = (const char*)(Blo + (size_t)n0 * Kk);
    const size_t rstride = (size_t)Kk * 2;
    const int nk = Kk / GM_BK;

    auto load_chunk = [&](int kt, int buf) {
        const uint32_t base = sb + buf * GM_BUF_BYTES;
#pragma unroll
        for (int tgt = 0; tgt < 4; ++tgt) {
            const char* gp = srcs[tgt] + (size_t)kt * 128;
            const uint32_t tb = base + tgt * GM_TILE_BYTES;
#pragma unroll
            for (int p = 0; p < 4; ++p) {
                int idx = tid + p * 256;
                int row = idx >> 3;
                int c16 = (idx & 7) << 4;
                cp_async16(tb + row * 128 + (c16 ^ ((row & 7) << 4)),
                           gp + (size_t)row * rstride + c16);
            }
        }
        cp_commit();
    };

    float acc[4][4][4];
#pragma unroll
    for (int i = 0; i < 4; ++i)
#pragma unroll
        for (int j = 0; j < 4; ++j)
#pragma unroll
            for (int k = 0; k < 4; ++k) acc[i][j][k] = 0.f;

    load_chunk(0, 0);

    const int a_row = lane & 15;
    const int a_csel = ((lane >> 4) & 1) << 4;
    const int b_row = (lane & 7) + (((lane >> 4) & 1) << 3);
    const int b_csel = ((lane >> 3) & 1) << 4;

    for (int kt = 0; kt < nk; ++kt) {
        const int buf = kt & 1;
        if (kt + 1 < nk) { load_chunk(kt + 1, buf ^ 1); cp_wait<1>(); }
        else             { cp_wait<0>(); }
        __syncthreads();

        const uint32_t base = sb + buf * GM_BUF_BYTES;
        const uint32_t aHiB = base;
        const uint32_t aLoB = base + GM_TILE_BYTES;
        const uint32_t bHiB = base + 2 * GM_TILE_BYTES;
        const uint32_t bLoB = base + 3 * GM_TILE_BYTES;

#pragma unroll
        for (int ks = 0; ks < 4; ++ks) {
            const int acol = ks * 32 + a_csel;
            const int bcol = ks * 32 + b_csel;
            uint32_t ahi[4][4], alo[4][4];
#pragma unroll
            for (int mt = 0; mt < 4; ++mt) {
                int row = wm + mt * 16 + a_row;
                uint32_t off = row * 128 + (acol ^ ((row & 7) << 4));
                ldsm4(ahi[mt], aHiB + off);
                ldsm4(alo[mt], aLoB + off);
            }
            uint32_t bhi[2][4], blo[2][4];
#pragma unroll
            for (int np = 0; np < 2; ++np) {
                int row = wn + np * 16 + b_row;
                uint32_t off = row * 128 + (bcol ^ ((row & 7) << 4));
                ldsm4(bhi[np], bHiB + off);
                ldsm4(blo[np], bLoB + off);
            }
#pragma unroll
            for (int mt = 0; mt < 4; ++mt)
#pragma unroll
                for (int np = 0; np < 2; ++np)
#pragma unroll
                    for (int s = 0; s < 2; ++s) {
                        int nt = np * 2 + s;
                        mma16816(acc[mt][nt], ahi[mt], &bhi[np][s * 2]);
                        mma16816(acc[mt][nt], ahi[mt], &blo[np][s * 2]);
                        mma16816(acc[mt][nt], alo[mt], &bhi[np][s * 2]);
                    }
        }
        __syncthreads();
    }

#pragma unroll
    for (int mt = 0; mt < 4; ++mt) {
        const int rg = m0 + wm + mt * 16 + (lane >> 2);
#pragma unroll
        for (int nt = 0; nt < 4; ++nt) {
            const int cg = n0 + wn + nt * 8 + (lane & 3) * 2;
            const float2 bv = *(const float2*)(bias + cg);
            float2 o0, o1;
            o0.x = acc[mt][nt][0] + bv.x;
            o0.y = acc[mt][nt][1] + bv.y;
            o1.x = acc[mt][nt][2] + bv.x;
            o1.y = acc[mt][nt][3] + bv.y;
            *(float2*)(C + (size_t)rg * Nn + cg) = o0;
            *(float2*)(C + (size_t)(rg + 8) * Nn + cg) = o1;
        }
    }
}

// ---------------- tensor-core persistent LSTM recurrence ----------------
// 128 CTAs x 256 threads. CTA owns 8 hidden units -> 32 gate rows (n = q*8+j).
// W_hh split-bf16 resident in smem; h streamed as global bf16 hi/lo (double buffered)
// via cp.async; gates = h @ Whh^T on mma.sync with 3-term split; one gbar per step.
__global__ void __launch_bounds__(256, 1) lstm_rec_tc(
    const float* __restrict__ xg, const float* __restrict__ Whh,
    const float* __restrict__ h0, const float* __restrict__ c0,
    float* __restrict__ y, float* __restrict__ hT, float* __restrict__ cT)
{
    extern __shared__ char smem[];
    const uint32_t sb = smem_u32(smem);
    float* sres = (float*)(smem + SM_RES);
    const int tid  = threadIdx.x;
    const int wid  = tid >> 5;
    const int lane = tid & 31;
    const int cta  = blockIdx.x;

    const unsigned e0 = *((volatile unsigned*)&g_epoch);

    // ---- prologue: convert this CTA's 32 W_hh rows to split-bf16 in smem ----
    // layout: comp (hi=0/lo=1) stride 64KB; [kc 0..7][r 0..31][256B] swizzled
    for (int i = tid; i < 32 * 256; i += 256) {
        int r  = i >> 8;                // 0..31  (n = q*8 + j)
        int c4 = i & 255;               // float4 index along K
        int gr = (r >> 3) * H + cta * 8 + (r & 7);
        float4 v = *(const float4*)(Whh + (size_t)gr * H + c4 * 4);
        int e  = c4 * 4;
        int kc = e >> 7;
        uint32_t bo = (uint32_t)((e & 127) * 2);        // byte offset in 256B row, 8B aligned
        uint32_t off = (uint32_t)(kc * 8192 + r * 256) + (bo ^ (uint32_t)((r & 7) << 4));
        __nv_bfloat16 hx = __float2bfloat16(v.x), hy = __float2bfloat16(v.y);
        __nv_bfloat16 hz = __float2bfloat16(v.z), hw = __float2bfloat16(v.w);
        *(__nv_bfloat162*)(smem + SM_W + off)     = __nv_bfloat162(hx, hy);
        *(__nv_bfloat162*)(smem + SM_W + off + 4) = __nv_bfloat162(hz, hw);
        *(__nv_bfloat162*)(smem + SM_W + 65536 + off) =
            __nv_bfloat162(__float2bfloat16(v.x - __bfloat162float(hx)),
                           __float2bfloat16(v.y - __bfloat162float(hy)));
        *(__nv_bfloat162*)(smem + SM_W + 65536 + off + 4) =
            __nv_bfloat162(__float2bfloat16(v.z - __bfloat162float(hz)),
                           __float2bfloat16(v.w - __bfloat162float(hw)));
    }

    // ---- init: c regs + h0 -> global bf16 buffer 0 (this CTA's 8 columns) ----
    float creg[2];
#pragma unroll
    for (int u = 0; u < 2; ++u) {
        int idx = tid + u * 256;        // 0..511 over (b, j)
        int b = idx >> 3, j = idx & 7;
        int jg = cta * 8 + j;
        float hv = h0[b * H + jg];
        __nv_bfloat16 hh = __float2bfloat16(hv);
        g_hb16[0][0][b * H + jg] = hh;
        g_hb16[0][1][b * H + jg] = __float2bfloat16(hv - __bfloat162float(hh));
        creg[u] = c0[b * H + jg];
    }
    gbar(e0 + 1);

    // mma lane addressing (same scheme as gemm_mma, 256B rows)
    const int wm = (wid >> 1) * 16;     // warp m-offset (4 m-tiles)
    const int wn = (wid & 1) * 16;      // warp n-offset (2 n-tiles)
    const int a_row = lane & 15;
    const int a_csel = ((lane >> 4) & 1) << 4;
    const int b_row = (lane & 7) + (((lane >> 4) & 1) << 3);
    const int b_csel = ((lane >> 3) & 1) << 4;

    for (int t = 0; t < T; ++t) {
        const __nv_bfloat16* hsrc0 = &g_hb16[t & 1][0][0];
        const __nv_bfloat16* hsrc1 = &g_hb16[t & 1][1][0];
        __nv_bfloat16* hdst0 = &g_hb16[(t + 1) & 1][0][0];
        __nv_bfloat16* hdst1 = &g_hb16[(t + 1) & 1][1][0];

        // prefetch xg for this step into registers (consumed in epilogue)
        float xgv[2][4];
#pragma unroll
        for (int u = 0; u < 2; ++u) {
            int idx = tid + u * 256;
            int b = idx >> 3, j = idx & 7;
            const float* xp = xg + ((size_t)(b * T + t)) * G + cta * 8 + j;
#pragma unroll
            for (int q = 0; q < 4; ++q) xgv[u][q] = __ldg(xp + q * H);
        }

        auto load_h = [&](int kc, int buf) {
            const uint32_t base = sb + SM_Hb + buf * 32768;
#pragma unroll
            for (int comp = 0; comp < 2; ++comp) {
                const char* gp = (const char*)(comp ? hsrc1 : hsrc0) + kc * 256;
                const uint32_t tb = base + comp * 16384;
#pragma unroll
                for (int p = 0; p < 4; ++p) {
                    int idx = tid + p * 256;       // 0..1023
                    int row = idx >> 4;            // 0..63
                    int c16 = (idx & 15) << 4;     // 0..240
                    cp_async16(tb + row * 256 + (c16 ^ ((row & 7) << 4)),
                               gp + (size_t)row * 2048 + c16);
                }
            }
            cp_commit();
        };

        float acc[2][4];
#pragma unroll
        for (int s = 0; s < 2; ++s)
#pragma unroll
            for (int k = 0; k < 4; ++k) acc[s][k] = 0.f;

        load_h(0, 0);
        for (int kc = 0; kc < 8; ++kc) {
            const int buf = kc & 1;
            if (kc + 1 < 8) { load_h(kc + 1, buf ^ 1); cp_wait<1>(); }
            else            { cp_wait<0>(); }
            __syncthreads();

            const uint32_t hHi = sb + SM_Hb + buf * 32768;
            const uint32_t hLo = hHi + 16384;
            const uint32_t wHi = sb + SM_W + kc * 8192;
            const uint32_t wLo = wHi + 65536;

#pragma unroll
            for (int ks = 0; ks < 8; ++ks) {
                const int acol = ks * 32 + a_csel;
                const int bcol = ks * 32 + b_csel;
                uint32_t ah[4], al[4], bh[4], bl[4];
                int arow = wm + a_row;
                uint32_t aoff = arow * 256 + (acol ^ ((arow & 7) << 4));
                ldsm4(ah, hHi + aoff);
                ldsm4(al, hLo + aoff);
                int brow = wn + b_row;
                uint32_t boff = brow * 256 + (bcol ^ ((brow & 7) << 4));
                ldsm4(bh, wHi + boff);
                ldsm4(bl, wLo + boff);
#pragma unroll
                for (int s = 0; s < 2; ++s) {
                    mma16816(acc[s], ah, &bh[s * 2]);
                    mma16816(acc[s], ah, &bl[s * 2]);
                    mma16816(acc[s], al, &bh[s * 2]);
                }
            }
            __syncthreads();
        }

        // stage accumulators to smem (row stride 40 floats: conflict-free reads)
        {
            int r0 = wm + (lane >> 2);
            int cb = wn + (lane & 3) * 2;
#pragma unroll
            for (int s = 0; s < 2; ++s) {
                *(float2*)&sres[r0 * 40 + cb + s * 8]       = make_float2(acc[s][0], acc[s][1]);
                *(float2*)&sres[(r0 + 8) * 40 + cb + s * 8] = make_float2(acc[s][2], acc[s][3]);
            }
        }
        __syncthreads();

        // epilogue: activations + state update + h writeback
#pragma unroll
        for (int u = 0; u < 2; ++u) {
            int idx = tid + u * 256;
            int b = idx >> 3, j = idx & 7;
            int jg = cta * 8 + j;
            float iv = sres[b * 40 + j]      + xgv[u][0];
            float fv = sres[b * 40 + 8 + j]  + xgv[u][1];
            float gv = sres[b * 40 + 16 + j] + xgv[u][2];
            float ov = sres[b * 40 + 24 + j] + xgv[u][3];
            float ig = 1.f / (1.f + expf(-iv));
            float fg = 1.f / (1.f + expf(-fv));
            float gg = tanhf(gv);
            float og = 1.f / (1.f + expf(-ov));
            float cv = fg * creg[u] + ig * gg;
            creg[u] = cv;
            float hv = og * tanhf(cv);
            y[((size_t)(b * T + t)) * H + jg] = hv;
            __nv_bfloat16 hh = __float2bfloat16(hv);
            hdst0[b * H + jg] = hh;
            hdst1[b * H + jg] = __float2bfloat16(hv - __bfloat162float(hh));
            if (t == T - 1) { hT[b * H + jg] = hv; cT[b * H + jg] = cv; }
        }
        gbar(e0 + 2 + t);
    }
}

// ---------------- launch ----------------
extern "C" void kernel_launch(void* const* d_in, const int* in_sizes, int n_in,
                              void* d_out, int out_size) {
    const float* x    = (const float*)d_in[0];
    const float* h0   = (const float*)d_in[1];
    const float* c0   = (const float*)d_in[2];
    const float* Wih0 = (const float*)d_in[3];
    const float* Whh0 = (const float*)d_in[4];
    const float* b0   = (const float*)d_in[5];
    const float* Wih1 = (const float*)d_in[6];
    const float* Whh1 = (const float*)d_in[7];
    const float* b1   = (const float*)d_in[8];
    const float* Wout = (const float*)d_in[9];
    const float* bout = (const float*)d_in[10];

    float* out     = (float*)d_out;
    float* out_act = out;
    float* out_h   = out + (size_t)M * V;
    float* out_c   = out_h + 2 * B * H;

    float *xg, *y0, *y1;
    __nv_bfloat16 *ahi, *alo, *whi, *wlo;
    cudaGetSymbolAddress((void**)&xg, g_xg);
    cudaGetSymbolAddress((void**)&y0, g_y0);
    cudaGetSymbolAddress((void**)&y1, g_y1);
    cudaGetSymbolAddress((void**)&ahi, g_act_hi);
    cudaGetSymbolAddress((void**)&alo, g_act_lo);
    cudaGetSymbolAddress((void**)&whi, g_w_hi);
    cudaGetSymbolAddress((void**)&wlo, g_w_lo);

    cudaFuncSetAttribute(gemm_mma, cudaFuncAttributeMaxDynamicSharedMemorySize, (int)SMEM_GM);
    cudaFuncSetAttribute(lstm_rec_tc, cudaFuncAttributeMaxDynamicSharedMemorySize, (int)SMEM_TC);

    // ---- Layer 0 input GEMM: xg = x @ Wih0^T + b0  (K=128) ----
    split_bf16<<<(M * V / 4 + 255) / 256, 256>>>(x, ahi, alo, M * V / 4);
    split_bf16<<<(G * V / 4 + 255) / 256, 256>>>(Wih0, whi, wlo, G * V / 4);
    gemm_mma<<<dim3(G / 128, M / 128), 256, SMEM_GM>>>(ahi, alo, whi, wlo, b0, xg, G, V);
    // ---- Layer 0 recurrence (tensor cores) ----
    lstm_rec_tc<<<NCTA, 256, SMEM_TC>>>(xg, Whh0, h0, c0, y0, out_h, out_c);
    // ---- Layer 1 input GEMM: xg = y0 @ Wih1^T + b1  (K=1024) ----
    split_bf16<<<(M * H / 4 + 255) / 256, 256>>>(y0, ahi, alo, M * H / 4);
    split_bf16<<<(G * H / 4 + 255) / 256, 256>>>(Wih1, whi, wlo, G * H / 4);
    gemm_mma<<<dim3(G / 128, M / 128), 256, SMEM_GM>>>(ahi, alo, whi, wlo, b1, xg, G, H);
    // ---- Layer 1 recurrence ----
    lstm_rec_tc<<<NCTA, 256, SMEM_TC>>>(xg, Whh1, h0 + B * H, c0 + B * H, y1,
                                        out_h + B * H, out_c + B * H);
    // ---- Head: act = y1 @ Wout^T + b_out  (N=128, K=1024) ----
    split_bf16<<<(M * H / 4 + 255) / 256, 256>>>(y1, ahi, alo, M * H / 4);
    split_bf16<<<(V * H / 4 + 255) / 256, 256>>>(Wout, whi, wlo, V * H / 4);
    gemm_mma<<<dim3(V / 128, M / 128), 256, SMEM_GM>>>(ahi, alo, whi, wlo, bout, out_act, V, H);
}

// round 7
// speedup vs baseline: 3.9464x; 1.0532x over previous
#include <cuda_runtime.h>
#include <cuda_bf16.h>
#include <cstdint>

#define B 64
#define T 256
#define V 128
#define H 1024
#define G 4096              // 4*H
#define M (B*T)             // 16384
#define NCTA 128

// ---------------- feed-forward mma GEMM tile config (3-stage pipeline) ----------------
#define GM_BM 128
#define GM_BN 128
#define GM_BK 64
#define GM_TILE_BYTES (128 * 128)
#define GM_BUF_BYTES (4 * GM_TILE_BYTES)     // Ahi, Alo, Bhi, Blo = 64KB
#define SMEM_GM (3 * GM_BUF_BYTES)           // 3-stage = 192KB

// ---------------- recurrence smem layout (bytes) ----------------
// W:   [2 comp][8 kc][32 rows][256B]   comp stride 64KB         -> 128 KB
// H:   [2 buf][2 comp][64 rows][256B]  buf stride 32KB           ->  64 KB
// RES: [2 half][64][40] fp32                                     ->  20 KB
#define SM_W   0
#define SM_Hb  131072
#define SM_RES 196608
#define SMEM_TC (SM_RES + 2 * 64 * 40 * 4)   // 217088

// ---------------- scratch (static device arrays; no cudaMalloc) ----------------
__device__ float g_xg[(size_t)M * G];
__device__ float g_y0[(size_t)M * H];
__device__ float g_y1[(size_t)M * H];
__device__ __align__(16) __nv_bfloat16 g_act_hi[(size_t)M * H];
__device__ __align__(16) __nv_bfloat16 g_act_lo[(size_t)M * H];
__device__ __align__(16) __nv_bfloat16 g_w_hi[(size_t)G * H];
__device__ __align__(16) __nv_bfloat16 g_w_lo[(size_t)G * H];
__device__ __align__(16) __nv_bfloat16 g_hb16[2][2][B * H];   // [buf][hi/lo][64*1024]
__device__ unsigned g_count;
__device__ unsigned g_epoch;

// ---------------- PTX helpers ----------------
__device__ __forceinline__ uint32_t smem_u32(const void* p) {
    uint32_t a;
    asm("{ .reg .u64 t; cvta.to.shared.u64 t, %1; cvt.u32.u64 %0, t; }" : "=r"(a) : "l"(p));
    return a;
}
__device__ __forceinline__ void cp_async16(uint32_t saddr, const void* gaddr) {
    asm volatile("cp.async.cg.shared.global [%0], [%1], 16;" :: "r"(saddr), "l"(gaddr) : "memory");
}
__device__ __forceinline__ void cp_commit() {
    asm volatile("cp.async.commit_group;" ::: "memory");
}
template <int N>
__device__ __forceinline__ void cp_wait() {
    asm volatile("cp.async.wait_group %0;" :: "n"(N) : "memory");
}
__device__ __forceinline__ void ldsm4(uint32_t* r, uint32_t addr) {
    asm volatile("ldmatrix.sync.aligned.m8n8.x4.shared.b16 {%0,%1,%2,%3}, [%4];"
        : "=r"(r[0]), "=r"(r[1]), "=r"(r[2]), "=r"(r[3]) : "r"(addr));
}
__device__ __forceinline__ void mma16816(float* d, const uint32_t* a, const uint32_t* b) {
    asm volatile("mma.sync.aligned.m16n8k16.row.col.f32.bf16.bf16.f32 "
        "{%0,%1,%2,%3}, {%4,%5,%6,%7}, {%8,%9}, {%0,%1,%2,%3};"
        : "+f"(d[0]), "+f"(d[1]), "+f"(d[2]), "+f"(d[3])
        : "r"(a[0]), "r"(a[1]), "r"(a[2]), "r"(a[3]), "r"(b[0]), "r"(b[1]));
}

// ---------------- software grid barrier (all 128 CTAs co-resident) ----------------
__device__ __forceinline__ void gbar(unsigned target) {
    __threadfence();
    __syncthreads();
    if (threadIdx.x == 0) {
        unsigned prev = atomicAdd(&g_count, 1u);
        if (prev == NCTA - 1) {
            g_count = 0u;
            __threadfence();
            *((volatile unsigned*)&g_epoch) = target;
        } else {
            while (*((volatile unsigned*)&g_epoch) != target) { __nanosleep(32); }
            __threadfence();
        }
    }
    __syncthreads();
}

// ---------------- fp32 -> bf16 hi/lo split (elementwise) ----------------
__global__ void __launch_bounds__(256) split_bf16(
    const float* __restrict__ in, __nv_bfloat16* __restrict__ hi,
    __nv_bfloat16* __restrict__ lo, int n4)
{
    int i = blockIdx.x * 256 + threadIdx.x;
    if (i >= n4) return;
    float4 v = ((const float4*)in)[i];
    __nv_bfloat16 h0 = __float2bfloat16(v.x);
    __nv_bfloat16 h1 = __float2bfloat16(v.y);
    __nv_bfloat16 h2 = __float2bfloat16(v.z);
    __nv_bfloat16 h3 = __float2bfloat16(v.w);
    __nv_bfloat16 l0 = __float2bfloat16(v.x - __bfloat162float(h0));
    __nv_bfloat16 l1 = __float2bfloat16(v.y - __bfloat162float(h1));
    __nv_bfloat16 l2 = __float2bfloat16(v.z - __bfloat162float(h2));
    __nv_bfloat16 l3 = __float2bfloat16(v.w - __bfloat162float(h3));
    ((__nv_bfloat162*)hi)[2 * i]     = __nv_bfloat162(h0, h1);
    ((__nv_bfloat162*)hi)[2 * i + 1] = __nv_bfloat162(h2, h3);
    ((__nv_bfloat162*)lo)[2 * i]     = __nv_bfloat162(l0, l1);
    ((__nv_bfloat162*)lo)[2 * i + 1] = __nv_bfloat162(l2, l3);
}

// ---------------- split-bf16 tensor GEMM (3-stage cp.async pipeline) ----------------
__global__ void __launch_bounds__(256, 1) gemm_mma(
    const __nv_bfloat16* __restrict__ Ahi, const __nv_bfloat16* __restrict__ Alo,
    const __nv_bfloat16* __restrict__ Bhi, const __nv_bfloat16* __restrict__ Blo,
    const float* __restrict__ bias, float* __restrict__ C, int Nn, int Kk)
{
    extern __shared__ char smem[];
    const uint32_t sb = smem_u32(smem);
    const int tid  = threadIdx.x;
    const int wid  = tid >> 5;
    const int lane = tid & 31;
    const int m0 = blockIdx.y * GM_BM;
    const int n0 = blockIdx.x * GM_BN;
    const int wm = (wid >> 2) * 64;
    const int wn = (wid & 3) * 32;

    const char* srcs[4];
    srcs[0] = (const char*)(Ahi + (size_t)m0 * Kk);
    srcs[1] = (const char*)(Alo + (size_t)m0 * Kk);
    srcs[2] = (const char*)(Bhi + (size_t)n0 * Kk);
    srcs[3] = (const char*)(Blo + (size_t)n0 * Kk);
    const size_t rstride = (size_t)Kk * 2;
    const int nk = Kk / GM_BK;

    auto load_chunk = [&](int kt, int buf) {
        const uint32_t base = sb + buf * GM_BUF_BYTES;
#pragma unroll
        for (int tgt = 0; tgt < 4; ++tgt) {
            const char* gp = srcs[tgt] + (size_t)kt * 128;
            const uint32_t tb = base + tgt * GM_TILE_BYTES;
#pragma unroll
            for (int p = 0; p < 4; ++p) {
                int idx = tid + p * 256;
                int row = idx >> 3;
                int c16 = (idx & 7) << 4;
                cp_async16(tb + row * 128 + (c16 ^ ((row & 7) << 4)),
                           gp + (size_t)row * rstride + c16);
            }
        }
        cp_commit();
    };

    float acc[4][4][4];
#pragma unroll
    for (int i = 0; i < 4; ++i)
#pragma unroll
        for (int j = 0; j < 4; ++j)
#pragma unroll
            for (int k = 0; k < 4; ++k) acc[i][j][k] = 0.f;

    load_chunk(0, 0);
    if (nk > 1) load_chunk(1, 1);

    const int a_row = lane & 15;
    const int a_csel = ((lane >> 4) & 1) << 4;
    const int b_row = (lane & 7) + (((lane >> 4) & 1) << 3);
    const int b_csel = ((lane >> 3) & 1) << 4;

    int buf = 0;
    for (int kt = 0; kt < nk; ++kt) {
        if (kt == nk - 1) cp_wait<0>(); else cp_wait<1>();
        __syncthreads();
        if (kt + 2 < nk) {
            int nb = buf + 2; if (nb >= 3) nb -= 3;
            load_chunk(kt + 2, nb);
        }

        const uint32_t base = sb + buf * GM_BUF_BYTES;
        const uint32_t aHiB = base;
        const uint32_t aLoB = base + GM_TILE_BYTES;
        const uint32_t bHiB = base + 2 * GM_TILE_BYTES;
        const uint32_t bLoB = base + 3 * GM_TILE_BYTES;

#pragma unroll
        for (int ks = 0; ks < 4; ++ks) {
            const int acol = ks * 32 + a_csel;
            const int bcol = ks * 32 + b_csel;
            uint32_t ahi[4][4], alo[4][4];
#pragma unroll
            for (int mt = 0; mt < 4; ++mt) {
                int row = wm + mt * 16 + a_row;
                uint32_t off = row * 128 + (acol ^ ((row & 7) << 4));
                ldsm4(ahi[mt], aHiB + off);
                ldsm4(alo[mt], aLoB + off);
            }
            uint32_t bhi[2][4], blo[2][4];
#pragma unroll
            for (int np = 0; np < 2; ++np) {
                int row = wn + np * 16 + b_row;
                uint32_t off = row * 128 + (bcol ^ ((row & 7) << 4));
                ldsm4(bhi[np], bHiB + off);
                ldsm4(blo[np], bLoB + off);
            }
#pragma unroll
            for (int mt = 0; mt < 4; ++mt)
#pragma unroll
                for (int np = 0; np < 2; ++np)
#pragma unroll
                    for (int s = 0; s < 2; ++s) {
                        int nt = np * 2 + s;
                        mma16816(acc[mt][nt], ahi[mt], &bhi[np][s * 2]);
                        mma16816(acc[mt][nt], ahi[mt], &blo[np][s * 2]);
                        mma16816(acc[mt][nt], alo[mt], &bhi[np][s * 2]);
                    }
        }
        if (++buf == 3) buf = 0;
    }

#pragma unroll
    for (int mt = 0; mt < 4; ++mt) {
        const int rg = m0 + wm + mt * 16 + (lane >> 2);
#pragma unroll
        for (int nt = 0; nt < 4; ++nt) {
            const int cg = n0 + wn + nt * 8 + (lane & 3) * 2;
            const float2 bv = *(const float2*)(bias + cg);
            float2 o0, o1;
            o0.x = acc[mt][nt][0] + bv.x;
            o0.y = acc[mt][nt][1] + bv.y;
            o1.x = acc[mt][nt][2] + bv.x;
            o1.y = acc[mt][nt][3] + bv.y;
            *(float2*)(C + (size_t)rg * Nn + cg) = o0;
            *(float2*)(C + (size_t)(rg + 8) * Nn + cg) = o1;
        }
    }
}

// ---------------- tensor-core persistent LSTM recurrence (512 thr, K-split halves) ----------------
// 128 CTAs x 512 threads. CTA owns 8 hidden units -> 32 gate rows.
// 16 warps: warp tile 16x16 over the 64x32 output; half = wid>>3 splits each
// 256B K-chunk (warps 0-7: k-steps 0-3, warps 8-15: k-steps 4-7). Partial
// accumulators reduced via smem in the epilogue.
__global__ void __launch_bounds__(512, 1) lstm_rec_tc(
    const float* __restrict__ xg, const float* __restrict__ Whh,
    const float* __restrict__ h0, const float* __restrict__ c0,
    float* __restrict__ y, float* __restrict__ hT, float* __restrict__ cT)
{
    extern __shared__ char smem[];
    const uint32_t sb = smem_u32(smem);
    float* sres = (float*)(smem + SM_RES);
    const int tid  = threadIdx.x;
    const int wid  = tid >> 5;
    const int lane = tid & 31;
    const int cta  = blockIdx.x;

    const unsigned e0 = *((volatile unsigned*)&g_epoch);

    // ---- prologue: convert this CTA's 32 W_hh rows to split-bf16 in smem ----
    for (int i = tid; i < 32 * 256; i += 512) {
        int r  = i >> 8;
        int c4 = i & 255;
        int gr = (r >> 3) * H + cta * 8 + (r & 7);
        float4 v = *(const float4*)(Whh + (size_t)gr * H + c4 * 4);
        int e  = c4 * 4;
        int kc = e >> 7;
        uint32_t bo = (uint32_t)((e & 127) * 2);
        uint32_t off = (uint32_t)(kc * 8192 + r * 256) + (bo ^ (uint32_t)((r & 7) << 4));
        __nv_bfloat16 hx = __float2bfloat16(v.x), hy = __float2bfloat16(v.y);
        __nv_bfloat16 hz = __float2bfloat16(v.z), hw = __float2bfloat16(v.w);
        *(__nv_bfloat162*)(smem + SM_W + off)     = __nv_bfloat162(hx, hy);
        *(__nv_bfloat162*)(smem + SM_W + off + 4) = __nv_bfloat162(hz, hw);
        *(__nv_bfloat162*)(smem + SM_W + 65536 + off) =
            __nv_bfloat162(__float2bfloat16(v.x - __bfloat162float(hx)),
                           __float2bfloat16(v.y - __bfloat162float(hy)));
        *(__nv_bfloat162*)(smem + SM_W + 65536 + off + 4) =
            __nv_bfloat162(__float2bfloat16(v.z - __bfloat162float(hz)),
                           __float2bfloat16(v.w - __bfloat162float(hw)));
    }

    // ---- init: one (b, j) per thread ----
    const int eb = tid >> 3;            // batch 0..63
    const int ej = tid & 7;             // unit 0..7
    const int ejg = cta * 8 + ej;
    float creg;
    {
        float hv = h0[eb * H + ejg];
        __nv_bfloat16 hh = __float2bfloat16(hv);
        g_hb16[0][0][eb * H + ejg] = hh;
        g_hb16[0][1][eb * H + ejg] = __float2bfloat16(hv - __bfloat162float(hh));
        creg = c0[eb * H + ejg];
    }
    gbar(e0 + 1);

    // warp mapping: half = K-split, wq = position in 4x2 tile grid
    const int half = wid >> 3;
    const int wq   = wid & 7;
    const int wm = (wq >> 1) * 16;
    const int wn = (wq & 1) * 16;
    const int a_row = lane & 15;
    const int a_csel = ((lane >> 4) & 1) << 4;
    const int b_row = (lane & 7) + (((lane >> 4) & 1) << 3);
    const int b_csel = ((lane >> 3) & 1) << 4;

    for (int t = 0; t < T; ++t) {
        const __nv_bfloat16* hsrc0 = &g_hb16[t & 1][0][0];
        const __nv_bfloat16* hsrc1 = &g_hb16[t & 1][1][0];
        __nv_bfloat16* hdst0 = &g_hb16[(t + 1) & 1][0][0];
        __nv_bfloat16* hdst1 = &g_hb16[(t + 1) & 1][1][0];

        // prefetch xg for this step (consumed in epilogue)
        float xgv[4];
        {
            const float* xp = xg + ((size_t)(eb * T + t)) * G + ejg;
#pragma unroll
            for (int q = 0; q < 4; ++q) xgv[q] = __ldg(xp + q * H);
        }

        auto load_h = [&](int kc, int buf) {
            const uint32_t base = sb + SM_Hb + buf * 32768;
#pragma unroll
            for (int p = 0; p < 4; ++p) {
                int idx = tid + p * 512;           // 0..2047
                int comp = idx >> 10;
                int ri = idx & 1023;
                int row = ri >> 4;                 // 0..63
                int c16 = (ri & 15) << 4;          // 0..240
                const char* gp = (const char*)(comp ? hsrc1 : hsrc0) + kc * 256;
                cp_async16(base + comp * 16384 + row * 256 + (c16 ^ ((row & 7) << 4)),
                           gp + (size_t)row * 2048 + c16);
            }
            cp_commit();
        };

        float acc[2][4];
#pragma unroll
        for (int s = 0; s < 2; ++s)
#pragma unroll
            for (int k = 0; k < 4; ++k) acc[s][k] = 0.f;

        load_h(0, 0);
        for (int kc = 0; kc < 8; ++kc) {
            const int buf = kc & 1;
            if (kc + 1 < 8) { load_h(kc + 1, buf ^ 1); cp_wait<1>(); }
            else            { cp_wait<0>(); }
            __syncthreads();

            const uint32_t hHi = sb + SM_Hb + buf * 32768;
            const uint32_t hLo = hHi + 16384;
            const uint32_t wHi = sb + SM_W + kc * 8192;
            const uint32_t wLo = wHi + 65536;

#pragma unroll
            for (int ks4 = 0; ks4 < 4; ++ks4) {
                const int ks = half * 4 + ks4;
                const int acol = ks * 32 + a_csel;
                const int bcol = ks * 32 + b_csel;
                uint32_t ah[4], al[4], bh[4], bl[4];
                int arow = wm + a_row;
                uint32_t aoff = arow * 256 + (acol ^ ((arow & 7) << 4));
                ldsm4(ah, hHi + aoff);
                ldsm4(al, hLo + aoff);
                int brow = wn + b_row;
                uint32_t boff = brow * 256 + (bcol ^ ((brow & 7) << 4));
                ldsm4(bh, wHi + boff);
                ldsm4(bl, wLo + boff);
#pragma unroll
                for (int s = 0; s < 2; ++s) {
                    mma16816(acc[s], ah, &bh[s * 2]);
                    mma16816(acc[s], ah, &bl[s * 2]);
                    mma16816(acc[s], al, &bh[s * 2]);
                }
            }
            __syncthreads();
        }

        // stage partial accumulators to smem: sres[half][row][40]
        {
            int r0 = wm + (lane >> 2);
            int cb = wn + (lane & 3) * 2;
            float* rp = sres + half * 2560;
#pragma unroll
            for (int s = 0; s < 2; ++s) {
                *(float2*)&rp[r0 * 40 + cb + s * 8]       = make_float2(acc[s][0], acc[s][1]);
                *(float2*)&rp[(r0 + 8) * 40 + cb + s * 8] = make_float2(acc[s][2], acc[s][3]);
            }
        }
        __syncthreads();

        // epilogue: reduce halves + activations + state update + writeback
        {
            float iv = sres[eb * 40 + ej]      + sres[2560 + eb * 40 + ej]      + xgv[0];
            float fv = sres[eb * 40 + 8 + ej]  + sres[2560 + eb * 40 + 8 + ej]  + xgv[1];
            float gv = sres[eb * 40 + 16 + ej] + sres[2560 + eb * 40 + 16 + ej] + xgv[2];
            float ov = sres[eb * 40 + 24 + ej] + sres[2560 + eb * 40 + 24 + ej] + xgv[3];
            float ig = 1.f / (1.f + expf(-iv));
            float fg = 1.f / (1.f + expf(-fv));
            float gg = tanhf(gv);
            float og = 1.f / (1.f + expf(-ov));
            float cv = fg * creg + ig * gg;
            creg = cv;
            float hv = og * tanhf(cv);
            y[((size_t)(eb * T + t)) * H + ejg] = hv;
            __nv_bfloat16 hh = __float2bfloat16(hv);
            hdst0[eb * H + ejg] = hh;
            hdst1[eb * H + ejg] = __float2bfloat16(hv - __bfloat162float(hh));
            if (t == T - 1) { hT[eb * H + ejg] = hv; cT[eb * H + ejg] = cv; }
        }
        gbar(e0 + 2 + t);
    }
}

// ---------------- launch ----------------
extern "C" void kernel_launch(void* const* d_in, const int* in_sizes, int n_in,
                              void* d_out, int out_size) {
    const float* x    = (const float*)d_in[0];
    const float* h0   = (const float*)d_in[1];
    const float* c0   = (const float*)d_in[2];
    const float* Wih0 = (const float*)d_in[3];
    const float* Whh0 = (const float*)d_in[4];
    const float* b0   = (const float*)d_in[5];
    const float* Wih1 = (const float*)d_in[6];
    const float* Whh1 = (const float*)d_in[7];
    const float* b1   = (const float*)d_in[8];
    const float* Wout = (const float*)d_in[9];
    const float* bout = (const float*)d_in[10];

    float* out     = (float*)d_out;
    float* out_act = out;
    float* out_h   = out + (size_t)M * V;
    float* out_c   = out_h + 2 * B * H;

    float *xg, *y0, *y1;
    __nv_bfloat16 *ahi, *alo, *whi, *wlo;
    cudaGetSymbolAddress((void**)&xg, g_xg);
    cudaGetSymbolAddress((void**)&y0, g_y0);
    cudaGetSymbolAddress((void**)&y1, g_y1);
    cudaGetSymbolAddress((void**)&ahi, g_act_hi);
    cudaGetSymbolAddress((void**)&alo, g_act_lo);
    cudaGetSymbolAddress((void**)&whi, g_w_hi);
    cudaGetSymbolAddress((void**)&wlo, g_w_lo);

    cudaFuncSetAttribute(gemm_mma, cudaFuncAttributeMaxDynamicSharedMemorySize, (int)SMEM_GM);
    cudaFuncSetAttribute(lstm_rec_tc, cudaFuncAttributeMaxDynamicSharedMemorySize, (int)SMEM_TC);

    // ---- Layer 0 input GEMM: xg = x @ Wih0^T + b0  (K=128) ----
    split_bf16<<<(M * V / 4 + 255) / 256, 256>>>(x, ahi, alo, M * V / 4);
    split_bf16<<<(G * V / 4 + 255) / 256, 256>>>(Wih0, whi, wlo, G * V / 4);
    gemm_mma<<<dim3(G / 128, M / 128), 256, SMEM_GM>>>(ahi, alo, whi, wlo, b0, xg, G, V);
    // ---- Layer 0 recurrence (tensor cores) ----
    lstm_rec_tc<<<NCTA, 512, SMEM_TC>>>(xg, Whh0, h0, c0, y0, out_h, out_c);
    // ---- Layer 1 input GEMM: xg = y0 @ Wih1^T + b1  (K=1024) ----
    split_bf16<<<(M * H / 4 + 255) / 256, 256>>>(y0, ahi, alo, M * H / 4);
    split_bf16<<<(G * H / 4 + 255) / 256, 256>>>(Wih1, whi, wlo, G * H / 4);
    gemm_mma<<<dim3(G / 128, M / 128), 256, SMEM_GM>>>(ahi, alo, whi, wlo, b1, xg, G, H);
    // ---- Layer 1 recurrence ----
    lstm_rec_tc<<<NCTA, 512, SMEM_TC>>>(xg, Whh1, h0 + B * H, c0 + B * H, y1,
                                        out_h + B * H, out_c + B * H);
    // ---- Head: act = y1 @ Wout^T + b_out  (N=128, K=1024) ----
    split_bf16<<<(M * H / 4 + 255) / 256, 256>>>(y1, ahi, alo, M * H / 4);
    split_bf16<<<(V * H / 4 + 255) / 256, 256>>>(Wout, whi, wlo, V * H / 4);
    gemm_mma<<<dim3(V / 128, M / 128), 256, SMEM_GM>>>(ahi, alo, whi, wlo, bout, out_act, V, H);
}